// round 10
// baseline (speedup 1.0000x reference)
#include <cuda_runtime.h>
#include <math_constants.h>

// Shapes (fixed): x: [B=32, C=256, H=128, W=128] float32
#define B_   32
#define C_   256
#define HW_  16384   // 128*128
#define HW4_ 4096    // HW/4 (float4 groups)

#define POOL_BLOCKS 1024  // 8 warps/block, 1 channel per warp -> single wave
#define XN_BLOCKS 512     // 32 b * 16 blocks/b (R3 shape)
#define TAIL_BLOCKS 64    // single wave -> spin barriers safe

// Scratch (device globals — no allocation allowed)
__device__ float g_pooled[B_ * C_];      // 32 KB
__device__ float g_xn[B_ * HW_];         // 2 MB
__device__ float g_ssum[XN_BLOCKS];      // sigmoid partials
__device__ float g_mm[TAIL_BLOCKS * 2];  // per-block (min,max)
__device__ int   g_hist[256];
__device__ int   g_c1;                   // min/max phase counter
__device__ int   g_c2;                   // hist phase counter

// ---------------------------------------------------------------------------
// K1: pooled[b,c] = mean over HW. ONE WARP PER CHANNEL: no smem, no
//     __syncthreads, single co-resident wave (1024 blocks x 8 warps).
//     Block 0 zeroes histogram + counters for this graph replay.
// ---------------------------------------------------------------------------
__global__ void __launch_bounds__(256) k_pool(const float* __restrict__ x) {
    const int tid = threadIdx.x;
    if (blockIdx.x == 0) {
        g_hist[tid] = 0;
        if (tid == 0) { g_c1 = 0; g_c2 = 0; }
    }

    const int w = tid >> 5;
    const int l = tid & 31;
    const int bc = blockIdx.x * 8 + w;          // 0..8191

    const float4* __restrict__ p =
        reinterpret_cast<const float4*>(x) + (size_t)bc * HW4_;

    float s = 0.0f;
#pragma unroll 16
    for (int i = 0; i < 128; i++) {
        float4 v = p[l + i * 32];
        s += (v.x + v.y) + (v.z + v.w);
    }
#pragma unroll
    for (int o = 16; o > 0; o >>= 1)
        s += __shfl_down_sync(0xffffffffu, s, o);
    if (l == 0) g_pooled[bc] = s * (1.0f / (float)HW_);
}

// ---------------------------------------------------------------------------
// K2 (R3 exact): xn[b,sp] = (1/C) * sum_c x[b,c,sp] * pooled[b,c]
//     One thread per float4 spatial group; per-block sigmoid partials.
// ---------------------------------------------------------------------------
__global__ void __launch_bounds__(256) k_xn(const float* __restrict__ x) {
    const int b   = blockIdx.x >> 4;                        // 0..31
    const int grp = ((blockIdx.x & 15) << 8) + threadIdx.x; // 0..4095

    __shared__ float pw[C_];
    pw[threadIdx.x] = g_pooled[b * C_ + threadIdx.x];
    __syncthreads();

    const float4* __restrict__ xp =
        reinterpret_cast<const float4*>(x) + (size_t)b * C_ * HW4_ + grp;

    float ax = 0.0f, ay = 0.0f, az = 0.0f, aw = 0.0f;
#pragma unroll 8
    for (int c = 0; c < C_; c++) {
        float4 v = xp[(size_t)c * HW4_];
        float w = pw[c];
        ax = fmaf(v.x, w, ax);
        ay = fmaf(v.y, w, ay);
        az = fmaf(v.z, w, az);
        aw = fmaf(v.w, w, aw);
    }
    const float inv = 1.0f / (float)C_;
    float4 xn;
    xn.x = ax * inv; xn.y = ay * inv; xn.z = az * inv; xn.w = aw * inv;
    reinterpret_cast<float4*>(g_xn)[(size_t)b * HW4_ + grp] = xn;

    float sg = 1.0f / (1.0f + __expf(-xn.x))
             + 1.0f / (1.0f + __expf(-xn.y))
             + 1.0f / (1.0f + __expf(-xn.z))
             + 1.0f / (1.0f + __expf(-xn.w));

    __shared__ float sm[256];
    sm[threadIdx.x] = sg;
    __syncthreads();
#pragma unroll
    for (int o = 128; o > 0; o >>= 1) {
        if (threadIdx.x < o) sm[threadIdx.x] += sm[threadIdx.x + o];
        __syncthreads();
    }
    if (threadIdx.x == 0) g_ssum[blockIdx.x] = sm[0];
}

// ---------------------------------------------------------------------------
// K3 (merged tail, 64 blocks = single wave):
//   1) entro for own 256 spatial slots (smem, no DRAM round-trip)
//   2) publish block min/max; spin until all 64 published; reduce redundantly
//   3) histogram own slots (smem) -> flush to global
//   4) last-done block: entropy + nz + sigmoid mean -> out
// ---------------------------------------------------------------------------
__global__ void __launch_bounds__(256) k_tail(float* __restrict__ out) {
    const int tid = threadIdx.x;
    const int sp  = blockIdx.x * 256 + tid;

    __shared__ float e_s[256];
    __shared__ float smin[256], smax[256];
    __shared__ int   hist[256];
    hist[tid] = 0;

    // entro = mean over batches
    float a = 0.0f;
#pragma unroll
    for (int b = 0; b < B_; b++) a += g_xn[(size_t)b * HW_ + sp];
    const float v = a * (1.0f / (float)B_);
    e_s[tid] = v;
    smin[tid] = v;
    smax[tid] = v;
    __syncthreads();
#pragma unroll
    for (int o = 128; o > 0; o >>= 1) {
        if (tid < o) {
            smin[tid] = fminf(smin[tid], smin[tid + o]);
            smax[tid] = fmaxf(smax[tid], smax[tid + o]);
        }
        __syncthreads();
    }
    if (tid == 0) {
        g_mm[blockIdx.x * 2 + 0] = smin[0];
        g_mm[blockIdx.x * 2 + 1] = smax[0];
        __threadfence();
        atomicAdd(&g_c1, 1);
        while (atomicAdd(&g_c1, 0) < TAIL_BLOCKS) __nanosleep(64);
    }
    __syncthreads();
    __threadfence();

    // reduce all 64 (min,max) pairs (redundant per block, cheap)
    if (tid < 64) {
        smin[tid] = __ldcg(&g_mm[tid * 2 + 0]);
        smax[tid] = __ldcg(&g_mm[tid * 2 + 1]);
    }
    __syncthreads();
#pragma unroll
    for (int o = 32; o > 0; o >>= 1) {
        if (tid < o) {
            smin[tid] = fminf(smin[tid], smin[tid + o]);
            smax[tid] = fmaxf(smax[tid], smax[tid + o]);
        }
        __syncthreads();
    }
    const float emin = smin[0];
    const float denom = smax[0] - emin;

    // histogram (256 uniform bins over [0,255], last bin right-inclusive)
    float e = (e_s[tid] - emin) / denom * 255.0f;
    int bin = (int)floorf(e * (256.0f / 255.0f));
    bin = min(max(bin, 0), 255);
    atomicAdd(&hist[bin], 1);
    __syncthreads();

    if (hist[tid] != 0) atomicAdd(&g_hist[tid], hist[tid]);
    __threadfence();

    __shared__ int islast;
    if (tid == 0) islast = (atomicAdd(&g_c2, 1) == TAIL_BLOCKS - 1) ? 1 : 0;
    __syncthreads();
    if (!islast) return;
    __threadfence();

    // sigmoid-sum reduce (512 partials, deterministic tree)
    __shared__ double sd[256];
    sd[tid] = (double)g_ssum[tid] + (double)g_ssum[tid + 256];
    __syncthreads();
#pragma unroll
    for (int o = 128; o > 0; o >>= 1) {
        if (tid < o) sd[tid] += sd[tid + o];
        __syncthreads();
    }

    // entropy + nonzero count over global histogram
    __shared__ float ssum[256];
    __shared__ int   snz[256];
    int h = __ldcg(&g_hist[tid]);
    float hisv = (float)h * (1.0f / (float)HW_);
    ssum[tid] = hisv * (-logf(hisv + 1e-8f));
    snz[tid]  = (h != 0) ? 1 : 0;
    __syncthreads();
#pragma unroll
    for (int o = 128; o > 0; o >>= 1) {
        if (tid < o) {
            ssum[tid] += ssum[tid + o];
            snz[tid]  += snz[tid + o];
        }
        __syncthreads();
    }

    if (tid == 0) {
        float s = (float)(sd[0] / (double)((size_t)B_ * HW_));
        float entro_final = ssum[0] / (float)snz[0];
        out[0] = s + entro_final * 10.0f;
    }
}

// ---------------------------------------------------------------------------
extern "C" void kernel_launch(void* const* d_in, const int* in_sizes, int n_in,
                              void* d_out, int out_size) {
    const float* x = (const float*)d_in[0];
    float* out = (float*)d_out;

    k_pool<<<POOL_BLOCKS, 256>>>(x);
    k_xn<<<XN_BLOCKS, 256>>>(x);
    k_tail<<<TAIL_BLOCKS, 256>>>(out);
}

// round 11
// speedup vs baseline: 1.0641x; 1.0641x over previous
#include <cuda_runtime.h>
#include <math_constants.h>

// Shapes (fixed): x: [B=32, C=256, H=128, W=128] float32
#define B_   32
#define C_   256
#define HW_  16384   // 128*128
#define HW4_ 4096    // HW/4 (float4 groups)

#define XN_BLOCKS 512    // 32 b * 16 blocks/b
#define ENTRO_BLOCKS 64
#define HIST_BLOCKS  64

// Scratch (device globals — no allocation allowed)
__device__ float g_pooled[B_ * C_];      // 32 KB
__device__ float g_xn[B_ * HW_];         // 2 MB
__device__ float g_ssum[XN_BLOCKS];      // sigmoid partials
__device__ float g_entro[HW_];           // 64 KB
__device__ float g_mm[ENTRO_BLOCKS * 2]; // per-block (min,max)
__device__ int   g_hist[256];

// ---------------------------------------------------------------------------
// K1: pooled[b,c] = mean over HW. One block per (b,c), full occupancy shape.
//     4 independent accumulators (breaks serial FADD chain); shfl-reduce +
//     single __syncthreads (was 8). Block 0 zeroes the histogram.
// ---------------------------------------------------------------------------
__global__ void __launch_bounds__(256) k_pool(const float* __restrict__ x) {
    const int tid = threadIdx.x;
    if (blockIdx.x == 0) g_hist[tid] = 0;

    const int bc = blockIdx.x;   // 0..8191
    const float4* __restrict__ p =
        reinterpret_cast<const float4*>(x) + (size_t)bc * HW4_;

    float s0 = 0.f, s1 = 0.f, s2 = 0.f, s3 = 0.f;
#pragma unroll
    for (int i = 0; i < 4; i++) {
        float4 a = p[tid + (4 * i + 0) * 256];
        float4 b = p[tid + (4 * i + 1) * 256];
        float4 c = p[tid + (4 * i + 2) * 256];
        float4 d = p[tid + (4 * i + 3) * 256];
        s0 += (a.x + a.y) + (a.z + a.w);
        s1 += (b.x + b.y) + (b.z + b.w);
        s2 += (c.x + c.y) + (c.z + c.w);
        s3 += (d.x + d.y) + (d.z + d.w);
    }
    float s = (s0 + s1) + (s2 + s3);
#pragma unroll
    for (int o = 16; o > 0; o >>= 1)
        s += __shfl_down_sync(0xffffffffu, s, o);

    __shared__ float sw[8];
    if ((tid & 31) == 0) sw[tid >> 5] = s;
    __syncthreads();
    if (tid == 0) {
        float t = ((sw[0] + sw[1]) + (sw[2] + sw[3]))
                + ((sw[4] + sw[5]) + (sw[6] + sw[7]));
        g_pooled[bc] = t * (1.0f / (float)HW_);
    }
}

// ---------------------------------------------------------------------------
// K2 (R3 mainloop): xn[b,sp] = (1/C) * sum_c x[b,c,sp] * pooled[b,c]
//     One thread per float4 spatial group; sigmoid partials via shfl + 1 bar.
// ---------------------------------------------------------------------------
__global__ void __launch_bounds__(256) k_xn(const float* __restrict__ x) {
    const int b   = blockIdx.x >> 4;                        // 0..31
    const int grp = ((blockIdx.x & 15) << 8) + threadIdx.x; // 0..4095

    __shared__ float pw[C_];
    pw[threadIdx.x] = g_pooled[b * C_ + threadIdx.x];
    __syncthreads();

    const float4* __restrict__ xp =
        reinterpret_cast<const float4*>(x) + (size_t)b * C_ * HW4_ + grp;

    float ax = 0.0f, ay = 0.0f, az = 0.0f, aw = 0.0f;
#pragma unroll 8
    for (int c = 0; c < C_; c++) {
        float4 v = xp[(size_t)c * HW4_];
        float w = pw[c];
        ax = fmaf(v.x, w, ax);
        ay = fmaf(v.y, w, ay);
        az = fmaf(v.z, w, az);
        aw = fmaf(v.w, w, aw);
    }
    const float inv = 1.0f / (float)C_;
    float4 xn;
    xn.x = ax * inv; xn.y = ay * inv; xn.z = az * inv; xn.w = aw * inv;
    reinterpret_cast<float4*>(g_xn)[(size_t)b * HW4_ + grp] = xn;

    float sg = 1.0f / (1.0f + __expf(-xn.x))
             + 1.0f / (1.0f + __expf(-xn.y))
             + 1.0f / (1.0f + __expf(-xn.z))
             + 1.0f / (1.0f + __expf(-xn.w));
#pragma unroll
    for (int o = 16; o > 0; o >>= 1)
        sg += __shfl_down_sync(0xffffffffu, sg, o);

    __shared__ float sw[8];
    if ((threadIdx.x & 31) == 0) sw[threadIdx.x >> 5] = sg;
    __syncthreads();
    if (threadIdx.x == 0) {
        float t = ((sw[0] + sw[1]) + (sw[2] + sw[3]))
                + ((sw[4] + sw[5]) + (sw[6] + sw[7]));
        g_ssum[blockIdx.x] = t;
    }
}

// ---------------------------------------------------------------------------
// K3: entro[sp] = mean over b of xn[b,sp]; per-block min/max partials.
// ---------------------------------------------------------------------------
__global__ void __launch_bounds__(256) k_entro() {
    const int sp = blockIdx.x * 256 + threadIdx.x;
    float a = 0.0f;
#pragma unroll
    for (int b = 0; b < B_; b++) a += g_xn[(size_t)b * HW_ + sp];
    float v = a * (1.0f / (float)B_);
    g_entro[sp] = v;

    __shared__ float smin[256], smax[256];
    smin[threadIdx.x] = v;
    smax[threadIdx.x] = v;
    __syncthreads();
#pragma unroll
    for (int o = 128; o > 0; o >>= 1) {
        if (threadIdx.x < o) {
            smin[threadIdx.x] = fminf(smin[threadIdx.x], smin[threadIdx.x + o]);
            smax[threadIdx.x] = fmaxf(smax[threadIdx.x], smax[threadIdx.x + o]);
        }
        __syncthreads();
    }
    if (threadIdx.x == 0) {
        g_mm[blockIdx.x * 2 + 0] = smin[0];
        g_mm[blockIdx.x * 2 + 1] = smax[0];
    }
}

// ---------------------------------------------------------------------------
// K4: 64 blocks: reduce min/max partials (redundant, cheap), bin 256 entro
//     elements each into shared histogram, flush to global histogram.
// ---------------------------------------------------------------------------
__global__ void __launch_bounds__(256) k_hist() {
    const int tid = threadIdx.x;

    __shared__ float smin[64], smax[64];
    __shared__ int hist[256];
    hist[tid] = 0;
    if (tid < 64) {
        smin[tid] = g_mm[tid * 2 + 0];
        smax[tid] = g_mm[tid * 2 + 1];
    }
    __syncthreads();
#pragma unroll
    for (int o = 32; o > 0; o >>= 1) {
        if (tid < o) {
            smin[tid] = fminf(smin[tid], smin[tid + o]);
            smax[tid] = fmaxf(smax[tid], smax[tid + o]);
        }
        __syncthreads();
    }
    const float emin = smin[0];
    const float denom = smax[0] - emin;

    float e = (g_entro[blockIdx.x * 256 + tid] - emin) / denom * 255.0f;
    int bin = (int)floorf(e * (256.0f / 255.0f));
    bin = min(max(bin, 0), 255);
    atomicAdd(&hist[bin], 1);
    __syncthreads();

    if (hist[tid] != 0) atomicAdd(&g_hist[tid], hist[tid]);
}

// ---------------------------------------------------------------------------
// K5: entropy over 256 bins + nz, sigmoid-sum reduce (512 partials), output.
// ---------------------------------------------------------------------------
__global__ void __launch_bounds__(256) k_out(float* __restrict__ out) {
    const int tid = threadIdx.x;

    __shared__ double sd[256];
    sd[tid] = (double)g_ssum[tid] + (double)g_ssum[tid + 256];
    __syncthreads();
#pragma unroll
    for (int o = 128; o > 0; o >>= 1) {
        if (tid < o) sd[tid] += sd[tid + o];
        __syncthreads();
    }

    __shared__ float ssum[256];
    __shared__ int   snz[256];
    int h = g_hist[tid];
    float hisv = (float)h * (1.0f / (float)HW_);
    ssum[tid] = hisv * (-logf(hisv + 1e-8f));
    snz[tid]  = (h != 0) ? 1 : 0;
    __syncthreads();
#pragma unroll
    for (int o = 128; o > 0; o >>= 1) {
        if (tid < o) {
            ssum[tid] += ssum[tid + o];
            snz[tid]  += snz[tid + o];
        }
        __syncthreads();
    }

    if (tid == 0) {
        float s = (float)(sd[0] / (double)((size_t)B_ * HW_));
        float entro_final = ssum[0] / (float)snz[0];
        out[0] = s + entro_final * 10.0f;
    }
}

// ---------------------------------------------------------------------------
extern "C" void kernel_launch(void* const* d_in, const int* in_sizes, int n_in,
                              void* d_out, int out_size) {
    const float* x = (const float*)d_in[0];
    float* out = (float*)d_out;

    k_pool<<<B_ * C_, 256>>>(x);
    k_xn<<<XN_BLOCKS, 256>>>(x);
    k_entro<<<ENTRO_BLOCKS, 256>>>();
    k_hist<<<HIST_BLOCKS, 256>>>();
    k_out<<<1, 256>>>(out);
}